// round 4
// baseline (speedup 1.0000x reference)
#include <cuda_runtime.h>

// SpearmanCorrelation, algebraically collapsed.
//
// Per (b,f) the rank vector r is a permutation of 0..E-1, so
//   weight[j,k]   = H[r_j, r_k],   H[a,c] = 1/(|a-c|+1)        (fixed)
//   corr[b,f,j,k] = Ct[r_j, r_k],  Ct[a,b]= (H*H)[a,b]-S[a]S[b]/(E-1)
//   out[b,j,k]    = sum_f Cs[r_{bfj}, r_{bfk}],  Cs = Ct / F
//
// Cs symmetric 128x128 fp32 (64KB, smem) -> out symmetric: j<=k + mirror.
// One fused kernel per batch: ranks (u64 composite keys, exact stable-argsort
// tie-break) computed in smem while cp.async streams Cs in.

#define BB 128
#define EE 128
#define FF 32

__device__ float g_C[EE * EE];

// ---------------------------------------------------------------------------
// Kernel 1: fixed table Cs = (H*H - S S^T/(E-1)) / F. 128 x 128 threads.
// ---------------------------------------------------------------------------
__global__ void build_C_kernel() {
    const int a = blockIdx.x;
    const int b = threadIdx.x;
    float g = 0.f, sa = 0.f, sb = 0.f;
    #pragma unroll 8
    for (int c = 0; c < EE; ++c) {
        const float ha = 1.0f / (float)(abs(a - c) + 1);
        const float hb = 1.0f / (float)(abs(b - c) + 1);
        g += ha * hb;
        sa += ha;
        sb += hb;
    }
    g_C[a * EE + b] = (g - sa * sb * (1.0f / (float)(EE - 1))) * (1.0f / (float)FF);
}

// ---------------------------------------------------------------------------
// Kernel 2 (fused): one block per batch, 256 threads.
//   Phase A: cp.async Cs (64KB) smem <- g_C            (overlaps B+C)
//   Phase B: build u64 sort keys in smem [e][f]
//   Phase C: ranks: thread (f=tid>>3, ebase=(tid&7)*16) counts 16 keys
//            against all 128; packed uint4 store -> rs[f][e] (conflict-free)
//   Phase D: gather-accumulate out[j,k] += Cs[r_fj, r_fk], j<=k triangle
//   Phase E: store + mirror
// smem: Cs 65536 | skey 32768 | rs 4096 = 102400 B
// ---------------------------------------------------------------------------
__global__ __launch_bounds__(256) void fused_kernel(const float* __restrict__ x,
                                                    float* __restrict__ out) {
    extern __shared__ unsigned char smem[];
    float* Cs = (float*)smem;                                   // 65536 B
    unsigned long long* skey = (unsigned long long*)(smem + 65536);  // 32768 B
    unsigned char* rs = smem + 65536 + 32768;                   // 4096 B

    const int b = blockIdx.x;
    const int tid = threadIdx.x;

    // ---- Phase A: async-copy C table (16B granules) ----
    {
        const unsigned cs_s = (unsigned)__cvta_generic_to_shared(Cs);
        const float4* src = (const float4*)g_C;
        #pragma unroll
        for (int it = 0; it < 16; ++it) {
            const int i = tid + it * 256;   // 0..4095
            asm volatile("cp.async.cg.shared.global [%0], [%1], 16;"
                         :: "r"(cs_s + i * 16), "l"(src + i));
        }
        asm volatile("cp.async.commit_group;" ::: "memory");
    }

    // ---- Phase B: sort keys. key = sortable_u32(x) << 7 | e ----
    {
        const float4* xb4 = (const float4*)(x + (size_t)b * EE * FF);
        #pragma unroll
        for (int it = 0; it < 4; ++it) {
            const int i = tid + it * 256;     // 0..1023 (float4 index)
            const float4 v = xb4[i];
            const unsigned e = (unsigned)(i >> 3);  // (4i+j)>>5 == i>>3 for j<4
            const float vv[4] = {v.x, v.y, v.z, v.w};
            #pragma unroll
            for (int j = 0; j < 4; ++j) {
                unsigned u = __float_as_uint(vv[j]);
                u ^= (((int)u >> 31) | 0x80000000u);  // monotone float->uint
                skey[4 * i + j] = ((unsigned long long)u << 7) | e;
                // layout [e][f]: linear idx 4i+j = e*32 + f already
            }
        }
    }
    __syncthreads();

    // ---- Phase C: ranks. f = tid>>3 (0..31), ebase = (tid&7)*16 ----
    {
        const int f = tid >> 3;
        const int ebase = (tid & 7) * 16;

        unsigned long long mykey[16];
        int cnt[16];
        #pragma unroll
        for (int i = 0; i < 16; ++i) {
            mykey[i] = skey[(ebase + i) * FF + f];
            cnt[i] = 0;
        }
        #pragma unroll 4
        for (int e2 = 0; e2 < EE; ++e2) {
            const unsigned long long k2 = skey[e2 * FF + f];  // 4-addr multicast
            #pragma unroll
            for (int i = 0; i < 16; ++i) cnt[i] += (k2 < mykey[i]);
        }
        uint4 packed;
        packed.x = (unsigned)cnt[0]  | ((unsigned)cnt[1]  << 8) | ((unsigned)cnt[2]  << 16) | ((unsigned)cnt[3]  << 24);
        packed.y = (unsigned)cnt[4]  | ((unsigned)cnt[5]  << 8) | ((unsigned)cnt[6]  << 16) | ((unsigned)cnt[7]  << 24);
        packed.z = (unsigned)cnt[8]  | ((unsigned)cnt[9]  << 8) | ((unsigned)cnt[10] << 16) | ((unsigned)cnt[11] << 24);
        packed.w = (unsigned)cnt[12] | ((unsigned)cnt[13] << 8) | ((unsigned)cnt[14] << 16) | ((unsigned)cnt[15] << 24);
        *(uint4*)(rs + f * EE + ebase) = packed;   // contiguous per 8-lane phase
    }

    asm volatile("cp.async.wait_group 0;" ::: "memory");
    __syncthreads();

    // ---- Phase D: gather-accumulate, j<=k triangle (word granularity) ----
    const int k = tid & 127;
    const int jlo = (tid >> 7) * 64;
    const int kmax = k | 31;   // warp-uniform

    float acc[64];
    #pragma unroll
    for (int jj = 0; jj < 64; ++jj) acc[jj] = 0.f;

    for (int f = 0; f < FF; ++f) {
        const unsigned rk = rs[f * EE + k];          // per-lane byte load
        const float* ck = Cs + rk;                   // column rk of Cs
        const unsigned* rj4 = (const unsigned*)(rs + f * EE + jlo);
        #pragma unroll
        for (int w = 0; w < 16; ++w) {
            if (jlo + 4 * w <= kmax) {               // warp-uniform skip
                const unsigned v = rj4[w];           // broadcast
                acc[w * 4 + 0] += ck[((v      ) & 255u) << 7];
                acc[w * 4 + 1] += ck[((v >> 8 ) & 255u) << 7];
                acc[w * 4 + 2] += ck[((v >> 16) & 255u) << 7];
                acc[w * 4 + 3] += ck[( v >> 24        ) << 7];
            }
        }
    }

    // ---- Phase E: store triangle + mirror (1/F baked into Cs) ----
    float* ob = out + (size_t)b * EE * EE;
    #pragma unroll
    for (int jj = 0; jj < 64; ++jj) {
        const int j = jlo + jj;
        if (j <= k) {
            const float v = acc[jj];
            ob[j * EE + k] = v;                      // coalesced
            if (j < k) ob[k * EE + j] = v;           // mirrored (via L2)
        }
    }
}

// ---------------------------------------------------------------------------
extern "C" void kernel_launch(void* const* d_in, const int* in_sizes, int n_in,
                              void* d_out, int out_size) {
    (void)in_sizes; (void)n_in; (void)out_size;
    const float* x = (const float*)d_in[0];
    float* out = (float*)d_out;

    build_C_kernel<<<EE, EE>>>();

    const size_t smem_bytes = 65536 + 32768 + 4096;  // 102400
    cudaFuncSetAttribute(fused_kernel,
                         cudaFuncAttributeMaxDynamicSharedMemorySize,
                         (int)smem_bytes);
    fused_kernel<<<BB, 256, smem_bytes>>>(x, out);
}

// round 13
// speedup vs baseline: 1.6767x; 1.6767x over previous
#include <cuda_runtime.h>

// SpearmanCorrelation, algebraically collapsed.
//
// Per (b,f) the rank vector r is a permutation of 0..E-1, so
//   weight[j,k]   = H[r_j, r_k],   H[a,c] = 1/(|a-c|+1)        (fixed)
//   corr[b,f,j,k] = Ct[r_j, r_k],  Ct[a,b]= (H*H)[a,b]-S[a]S[b]/(E-1)
//   out[b,j,k]    = sum_f Cs[r_{bfj}, r_{bfk}],  Cs = Ct / F
//
// Cs symmetric 128x128 fp32 (64KB, smem) -> out symmetric: compute j<=k,
// mirror through a swizzled smem transpose (coalesced global stores only).
// One fused 1024-thread block per batch.

#define BB 128
#define EE 128
#define FF 32

__device__ float g_C[EE * EE];

// ---------------------------------------------------------------------------
// Kernel 1: fixed table Cs = (H*H - S S^T/(E-1)) / F, via smem recip table.
// ---------------------------------------------------------------------------
__global__ void build_C_kernel() {
    __shared__ float inv[EE + 1];
    const int a = blockIdx.x;
    const int b = threadIdx.x;
    inv[b + 1] = 1.0f / (float)(b + 1);
    __syncthreads();
    float g = 0.f, sa = 0.f, sb = 0.f;
    #pragma unroll 8
    for (int c = 0; c < EE; ++c) {
        const float ha = inv[abs(a - c) + 1];
        const float hb = inv[abs(b - c) + 1];
        g += ha * hb;
        sa += ha;
        sb += hb;
    }
    g_C[a * EE + b] =
        (g - sa * sb * (1.0f / (float)(EE - 1))) * (1.0f / (float)FF);
}

// ---------------------------------------------------------------------------
// Kernel 2 (fused): one 1024-thread block per batch.
//   A: cp.async Cs (64KB) <- g_C                  (overlaps B+C)
//   B: u64 sort keys (exact stable-argsort tie-break) -> skey[f][e]
//   C: ranks: warp f=tid>>5, each lane counts 4 keys vs all 128 (broadcast)
//   D: gather-accumulate acc[j] += Cs[rj*128 + rk], j<=k triangle,
//      16 j's per thread (k=tid&127, jlo=(tid>>7)*16), LDS.128 index prefetch
//   E: swizzled smem transpose (reusing Cs) -> fully coalesced stores
// smem: Cs 65536 | skey 32768 | rs 4096 = 102400 B
// ---------------------------------------------------------------------------
__global__ __launch_bounds__(1024, 1) void fused_kernel(
    const float* __restrict__ x, float* __restrict__ out) {
    extern __shared__ unsigned char smem[];
    float* Cs = (float*)smem;                                        // 65536 B
    unsigned long long* skey = (unsigned long long*)(smem + 65536);  // 32768 B, [f][e]
    unsigned char* rs = smem + 65536 + 32768;                        // 4096 B,  [f][e]

    const int b = blockIdx.x;
    const int tid = threadIdx.x;

    // ---- Phase A: async-copy C table (16B granules, 4 per thread) ----
    {
        const unsigned cs_s = (unsigned)__cvta_generic_to_shared(Cs);
        const float4* src = (const float4*)g_C;
        #pragma unroll
        for (int it = 0; it < 4; ++it) {
            const int i = tid + it * 1024;
            asm volatile("cp.async.cg.shared.global [%0], [%1], 16;"
                         :: "r"(cs_s + i * 16), "l"(src + i));
        }
        asm volatile("cp.async.commit_group;" ::: "memory");
    }

    // ---- Phase B: keys. key = sortable_u32(x) << 7 | e, layout [f][e] ----
    {
        const float4* xb4 = (const float4*)(x + (size_t)b * EE * FF);
        const float4 v = xb4[tid];          // linear 4*tid+j = e*32 + f
        const unsigned e = (unsigned)tid >> 3;
        const unsigned f0 = ((unsigned)tid & 7u) * 4u;
        const float vv[4] = {v.x, v.y, v.z, v.w};
        #pragma unroll
        for (int j = 0; j < 4; ++j) {
            unsigned u = __float_as_uint(vv[j]);
            u ^= (((int)u >> 31) | 0x80000000u);   // monotone float -> uint
            skey[(f0 + j) * EE + e] = ((unsigned long long)u << 7) | e;
        }
    }
    __syncthreads();

    // ---- Phase C: ranks. f = tid>>5 (warp-uniform), e0 = 4*lane ----
    {
        const int f = tid >> 5;
        const int e0 = (tid & 31) * 4;
        unsigned long long mykey[4];
        int cnt[4] = {0, 0, 0, 0};
        #pragma unroll
        for (int i = 0; i < 4; ++i) mykey[i] = skey[f * EE + e0 + i];
        #pragma unroll 4
        for (int e2 = 0; e2 < EE; ++e2) {
            const unsigned long long k2 = skey[f * EE + e2];  // broadcast
            #pragma unroll
            for (int i = 0; i < 4; ++i) cnt[i] += (k2 < mykey[i]);
        }
        const unsigned packed = (unsigned)cnt[0] | ((unsigned)cnt[1] << 8) |
                                ((unsigned)cnt[2] << 16) | ((unsigned)cnt[3] << 24);
        *(unsigned*)(rs + f * EE + e0) = packed;   // lane-contiguous store
    }
    asm volatile("cp.async.wait_group 0;" ::: "memory");
    __syncthreads();

    // ---- Phase D: gather-accumulate, j<=k triangle (word granularity) ----
    const int k = tid & 127;
    const int jlo = (tid >> 7) * 16;
    const int kmax = k | 31;   // warp-uniform

    float acc[16];
    #pragma unroll
    for (int i = 0; i < 16; ++i) acc[i] = 0.f;

    // Prefetch f=0 index words (rs + jlo is 16B-aligned -> LDS.128)
    unsigned rk_cur = rs[k];
    uint4 rj_cur = *(const uint4*)(rs + jlo);

    #pragma unroll 4
    for (int f = 0; f < FF; ++f) {
        const unsigned rk = rk_cur;
        const uint4 rj = rj_cur;
        if (f + 1 < FF) {   // prefetch next iteration's indices
            rk_cur = rs[(f + 1) * EE + k];
            rj_cur = *(const uint4*)(rs + (f + 1) * EE + jlo);
        }
        const float* ck = Cs + rk;                   // column rk of Cs
        const unsigned rjw[4] = {rj.x, rj.y, rj.z, rj.w};
        #pragma unroll
        for (int w = 0; w < 4; ++w) {
            if (jlo + 4 * w <= kmax) {               // warp-uniform skip
                const unsigned v = rjw[w];
                acc[w * 4 + 0] += ck[((v      ) & 255u) << 7];
                acc[w * 4 + 1] += ck[((v >> 8 ) & 255u) << 7];
                acc[w * 4 + 2] += ck[((v >> 16) & 255u) << 7];
                acc[w * 4 + 3] += ck[( v >> 24        ) << 7];
            }
        }
    }

    // ---- Phase E: swizzled transpose through smem (Cs is dead now) ----
    __syncthreads();   // all gathers done before overwriting Cs
    #pragma unroll
    for (int ii = 0; ii < 16; ++ii) {
        const int j = jlo + ii;
        if (j <= k) Cs[j * EE + ((k + j) & 127)] = acc[ii];  // CF banks
    }
    __syncthreads();
    float* ob = out + (size_t)b * EE * EE;
    #pragma unroll
    for (int ii = 0; ii < 16; ++ii) {
        const int j = jlo + ii;
        const float v = (j <= k) ? acc[ii] : Cs[k * EE + ((j + k) & 127)];
        ob[j * EE + k] = v;                          // fully coalesced
    }
}

// ---------------------------------------------------------------------------
extern "C" void kernel_launch(void* const* d_in, const int* in_sizes, int n_in,
                              void* d_out, int out_size) {
    (void)in_sizes; (void)n_in; (void)out_size;
    const float* x = (const float*)d_in[0];
    float* out = (float*)d_out;

    build_C_kernel<<<EE, EE>>>();

    const size_t smem_bytes = 65536 + 32768 + 4096;  // 102400
    cudaFuncSetAttribute(fused_kernel,
                         cudaFuncAttributeMaxDynamicSharedMemorySize,
                         (int)smem_bytes);
    fused_kernel<<<BB, 1024, smem_bytes>>>(x, out);
}